// round 3
// baseline (speedup 1.0000x reference)
#include <cuda_runtime.h>

// PrimitiveGate: apply complex 2x2 gate to qubit axis 12 of a 23-qubit state,
// batch 4. Layout: (DIM, BATCH) float32, re/im planes separate.
// Output: (2, DIM, BATCH) float32 -> [out_re | out_im].
//
// Axis 12 of 23 -> bit 10 of dim index. BATCH=4 floats -> one float4/row.
//
// HBM-bound streaming kernel (536 MB irreducible traffic). R3: ILP=2 pairs
// per thread (split-stream: p and p+NPAIRS/2) -> MLP_p1=8 front-batched
// LDG.128, half the CTAs, same perfect coalescing.

#define N_QUBITS 23
#define TARGET_BIT 10            // N_QUBITS - 1 - TARGET_Q(12)
#define DIM (1u << N_QUBITS)     // 8388608
#define NPAIRS (DIM >> 1)        // 4194304
#define HALF (NPAIRS >> 1)       // 2097152
#define LOWMASK ((1u << TARGET_BIT) - 1u)

__global__ void __launch_bounds__(256)
gate_kernel(const float4* __restrict__ sre,
            const float4* __restrict__ sim,
            const float*  __restrict__ mre,
            const float*  __restrict__ mim,
            float4* __restrict__ out)
{
    unsigned p0 = blockIdx.x * 256u + threadIdx.x;   // [0, HALF)
    unsigned p1 = p0 + HALF;                          // [HALF, NPAIRS)

    unsigned aidx0 = ((p0 & ~LOWMASK) << 1) | (p0 & LOWMASK);
    unsigned bidx0 = aidx0 | (1u << TARGET_BIT);
    unsigned aidx1 = ((p1 & ~LOWMASK) << 1) | (p1 & LOWMASK);
    unsigned bidx1 = aidx1 | (1u << TARGET_BIT);

    // 8 independent front-batched streaming loads (MLP = 8)
    float4 A_re0 = __ldcs(&sre[aidx0]);
    float4 B_re0 = __ldcs(&sre[bidx0]);
    float4 A_im0 = __ldcs(&sim[aidx0]);
    float4 B_im0 = __ldcs(&sim[bidx0]);
    float4 A_re1 = __ldcs(&sre[aidx1]);
    float4 B_re1 = __ldcs(&sre[bidx1]);
    float4 A_im1 = __ldcs(&sim[aidx1]);
    float4 B_im1 = __ldcs(&sim[bidx1]);

    float m00r = __ldg(&mre[0]), m01r = __ldg(&mre[1]);
    float m10r = __ldg(&mre[2]), m11r = __ldg(&mre[3]);
    float m00i = __ldg(&mim[0]), m01i = __ldg(&mim[1]);
    float m10i = __ldg(&mim[2]), m11i = __ldg(&mim[3]);

#define LANE(ar, ai, br, bi, o0r, o0i, o1r, o1i, f)                             \
    do {                                                                        \
        float s0r = ar.f, s0i = ai.f, s1r = br.f, s1i = bi.f;                   \
        o0r.f = fmaf(m00r, s0r, fmaf(-m00i, s0i, fmaf(m01r, s1r, -m01i * s1i)));\
        o0i.f = fmaf(m00r, s0i, fmaf( m00i, s0r, fmaf(m01r, s1i,  m01i * s1r)));\
        o1r.f = fmaf(m10r, s0r, fmaf(-m10i, s0i, fmaf(m11r, s1r, -m11i * s1i)));\
        o1i.f = fmaf(m10r, s0i, fmaf( m10i, s0r, fmaf(m11r, s1i,  m11i * s1r)));\
    } while (0)

    {
        float4 o0r, o0i, o1r, o1i;
        LANE(A_re0, A_im0, B_re0, B_im0, o0r, o0i, o1r, o1i, x);
        LANE(A_re0, A_im0, B_re0, B_im0, o0r, o0i, o1r, o1i, y);
        LANE(A_re0, A_im0, B_re0, B_im0, o0r, o0i, o1r, o1i, z);
        LANE(A_re0, A_im0, B_re0, B_im0, o0r, o0i, o1r, o1i, w);
        __stcs(&out[aidx0],       o0r);
        __stcs(&out[bidx0],       o1r);
        __stcs(&out[DIM + aidx0], o0i);
        __stcs(&out[DIM + bidx0], o1i);
    }
    {
        float4 o0r, o0i, o1r, o1i;
        LANE(A_re1, A_im1, B_re1, B_im1, o0r, o0i, o1r, o1i, x);
        LANE(A_re1, A_im1, B_re1, B_im1, o0r, o0i, o1r, o1i, y);
        LANE(A_re1, A_im1, B_re1, B_im1, o0r, o0i, o1r, o1i, z);
        LANE(A_re1, A_im1, B_re1, B_im1, o0r, o0i, o1r, o1i, w);
        __stcs(&out[aidx1],       o0r);
        __stcs(&out[bidx1],       o1r);
        __stcs(&out[DIM + aidx1], o0i);
        __stcs(&out[DIM + bidx1], o1i);
    }
#undef LANE
}

extern "C" void kernel_launch(void* const* d_in, const int* in_sizes, int n_in,
                              void* d_out, int out_size)
{
    const float4* sre = (const float4*)d_in[0];
    const float4* sim = (const float4*)d_in[1];
    const float*  mre = (const float*)d_in[2];
    const float*  mim = (const float*)d_in[3];
    float4* out = (float4*)d_out;

    dim3 grid(HALF / 256);  // 8192 blocks, exact
    gate_kernel<<<grid, 256>>>(sre, sim, mre, mim, out);
}

// round 4
// speedup vs baseline: 1.0027x; 1.0027x over previous
#include <cuda_runtime.h>

// PrimitiveGate: apply complex 2x2 gate to qubit axis 12 of a 23-qubit state,
// batch 4. State layout: (DIM, BATCH) float32, re and im planes separate.
// Output: (2, DIM, BATCH) float32 -> [out_re | out_im].
//
// Axis 12 of 23 (axis 0 = MSB) -> bit 10 of the dim index.
// BATCH=4 contiguous floats per dim index -> one float4 per (dim, batch-row).
//
// FINAL (reverted to R2 best): pure HBM-streaming kernel, 536 MB irreducible
// traffic, measured 82.5% of HBM spec (~6.5 TB/s). Session evidence:
//   R2: .cs streaming hints        -> neutral (L2 policy not the limiter)
//   R3: ILP=2 / MLP=8 per thread   -> regression (occ 80->63%, DRAM -2.6%)
// One pair per thread, 32 regs, 80% occ, exact float4 coalescing is the
// roofline configuration for this mixed R/W streaming pattern on B300.

#define N_QUBITS 23
#define TARGET_BIT 10            // N_QUBITS - 1 - TARGET_Q(12)
#define DIM (1u << N_QUBITS)     // 8388608
#define NPAIRS (DIM >> 1)        // 4194304
#define LOWMASK ((1u << TARGET_BIT) - 1u)

__global__ void __launch_bounds__(256)
gate_kernel(const float4* __restrict__ sre,
            const float4* __restrict__ sim,
            const float*  __restrict__ mre,
            const float*  __restrict__ mim,
            float4* __restrict__ out)
{
    unsigned p = blockIdx.x * 256u + threadIdx.x;

    // i0: insert a 0 at bit TARGET_BIT; i1 = i0 | (1<<TARGET_BIT)
    unsigned i0 = ((p & ~LOWMASK) << 1) | (p & LOWMASK);
    unsigned i1 = i0 | (1u << TARGET_BIT);

    // Front-batched independent streaming loads (MLP = 4), evict-first
    float4 a_re = __ldcs(&sre[i0]);
    float4 b_re = __ldcs(&sre[i1]);
    float4 a_im = __ldcs(&sim[i0]);
    float4 b_im = __ldcs(&sim[i1]);

    // 2x2 complex gate, row-major (tiny, hot in L1 — normal loads)
    float m00r = __ldg(&mre[0]), m01r = __ldg(&mre[1]);
    float m10r = __ldg(&mre[2]), m11r = __ldg(&mre[3]);
    float m00i = __ldg(&mim[0]), m01i = __ldg(&mim[1]);
    float m10i = __ldg(&mim[2]), m11i = __ldg(&mim[3]);

    float4 o0r, o0i, o1r, o1i;

#define LANE(f)                                                                 \
    do {                                                                        \
        float s0r = a_re.f, s0i = a_im.f, s1r = b_re.f, s1i = b_im.f;           \
        o0r.f = fmaf(m00r, s0r, fmaf(-m00i, s0i, fmaf(m01r, s1r, -m01i * s1i)));\
        o0i.f = fmaf(m00r, s0i, fmaf( m00i, s0r, fmaf(m01r, s1i,  m01i * s1r)));\
        o1r.f = fmaf(m10r, s0r, fmaf(-m10i, s0i, fmaf(m11r, s1r, -m11i * s1i)));\
        o1i.f = fmaf(m10r, s0i, fmaf( m10i, s0r, fmaf(m11r, s1i,  m11i * s1r)));\
    } while (0)

    LANE(x); LANE(y); LANE(z); LANE(w);
#undef LANE

    // out_re plane at [0, DIM), out_im plane at [DIM, 2*DIM) (in float4 units)
    // Streaming stores: full-line coalesced, evict-first.
    __stcs(&out[i0],       o0r);
    __stcs(&out[i1],       o1r);
    __stcs(&out[DIM + i0], o0i);
    __stcs(&out[DIM + i1], o1i);
}

extern "C" void kernel_launch(void* const* d_in, const int* in_sizes, int n_in,
                              void* d_out, int out_size)
{
    const float4* sre = (const float4*)d_in[0];
    const float4* sim = (const float4*)d_in[1];
    const float*  mre = (const float*)d_in[2];
    const float*  mim = (const float*)d_in[3];
    float4* out = (float4*)d_out;

    dim3 grid(NPAIRS / 256);  // 16384 blocks, exact
    gate_kernel<<<grid, 256>>>(sre, sim, mre, mim, out);
}